// round 11
// baseline (speedup 1.0000x reference)
#include <cuda_runtime.h>
#include <cuda_bf16.h>
#include <cstdint>

// ============================================================================
// 2-layer LSTM (H=32, T=7, F=1) + fc(H,1) + fc1(T,1), B=262144.
// R11 = R10 (best: 1284us) with gate-i/f weight pairs (q0,q1) moved to
// __constant__ memory (LDC port, separate from L1) — 24KB, fits const L1.5.
// Gates g/o pairs (q2,q3) stay in SMEM (LDS.128 broadcast). Per k-iter L1
// cost 10 -> 6 cycles. Prep kernel repacks -> staging; D2D memcpy -> cW.
// E=2 elems/thread, NT=320 (10 warps/SM), c-state in gmem scratch.
// ============================================================================

typedef unsigned long long u64;

#define NT 320          // threads per CTA (10 warps)
#define EPC (2 * NT)    // batch elements per CTA
#define BMAX 524288ull  // scratch capacity (>= B)

__device__ u64 g_cstate[32ull * BMAX];

// const weights: [m:3][c:8][k:32][p:2] ulonglong2, p=0:(i0,i1) p=1:(f0,f1)
__constant__ ulonglong2 cW[1536];     // 24KB
__device__ u64 g_wpack[3072];         // staging for cW (same layout, u64 view)

__device__ __forceinline__ u64 pk2(float lo, float hi) {
    u64 r; asm("mov.b64 %0,{%1,%2};" : "=l"(r) : "f"(lo), "f"(hi)); return r;
}
__device__ __forceinline__ u64 bc2(float v) { return pk2(v, v); }
__device__ __forceinline__ void upk2(u64 v, float& lo, float& hi) {
    asm("mov.b64 {%0,%1},%2;" : "=f"(lo), "=f"(hi) : "l"(v));
}
__device__ __forceinline__ u64 fma2(u64 a, u64 b, u64 c) {
    u64 d; asm("fma.rn.f32x2 %0,%1,%2,%3;" : "=l"(d) : "l"(a), "l"(b), "l"(c)); return d;
}
__device__ __forceinline__ u64 mul2(u64 a, u64 b) {
    u64 d; asm("mul.rn.f32x2 %0,%1,%2;" : "=l"(d) : "l"(a), "l"(b)); return d;
}
__device__ __forceinline__ float ex2f(float x) {
    float y; asm("ex2.approx.f32 %0,%1;" : "=f"(y) : "f"(x)); return y;
}
__device__ __forceinline__ float rcpf(float x) {
    float y; asm("rcp.approx.f32 %0,%1;" : "=f"(y) : "f"(x)); return y;
}
__device__ __forceinline__ float fsig(float x) {
    float e = ex2f(-1.4426950408889634f * x);
    return rcpf(1.0f + e);
}
__device__ __forceinline__ float ftanhx(float x) {
    float t = fminf(-2.8853900817779268f * x, 120.0f);
    float e = ex2f(t);
    float r = rcpf(1.0f + e);
    return fmaf(-e, r, r);
}
__device__ __forceinline__ u64 sig2(u64 z) {
    float a, b; upk2(z, a, b); return pk2(fsig(a), fsig(b));
}
__device__ __forceinline__ u64 tanh2(u64 z) {
    float a, b; upk2(z, a, b); return pk2(ftanhx(a), ftanhx(b));
}

template <bool DOACC>
__device__ __forceinline__ u64 lstm_upd(
    u64 zi, u64 zf, u64 zg, u64 zo, u64& c, u64 wo, u64& acc)
{
    u64 i2 = sig2(zi);
    u64 f2 = sig2(zf);
    u64 g2 = tanh2(zg);
    u64 o2 = sig2(zo);
    c = fma2(f2, c, mul2(i2, g2));
    u64 h2 = mul2(o2, tanh2(c));
    if (DOACC) acc = fma2(h2, wo, acc);
    return h2;
}

// ---- prep: repack gate-i/f weight pairs into g_wpack (cW layout) ----
// u64 idx = m*1024 + c*128 + k*4 + s, s=0..3: gate g=s>>1 (i,f), sub=s&1.
extern "C" __global__ void lstm_wpack_kernel(
    const float* __restrict__ Whh0, const float* __restrict__ Wih1,
    const float* __restrict__ Whh1)
{
    int d = blockIdx.x * 1024 + threadIdx.x;
    if (d >= 3072) return;
    int m = d >> 10, r = d & 1023;
    int c = r >> 7, k = (r >> 2) & 31, s = r & 3;
    int g = s >> 1, sub = s & 1;
    int r0 = g * 32 + 4 * c + 2 * sub;
    const float* W = (m == 0) ? Whh0 : (m == 1) ? Wih1 : Whh1;
    g_wpack[d] = pk2(W[r0 * 32 + k], W[(r0 + 1) * 32 + k]);
}

// SMEM layout (u64 units):
//  WLs  [3m][8c][32k][4s] gate-g/o halves (s=4..7)   3072
//  B0   [64]  (b_ih0+b_hh0) pairs                      64
//  WI0  [64]  W_ih0[:,0] pairs                         64
//  B1   [64]  (b_ih1+b_hh1) pairs                      64
//  WO   [7][16] fc1_w[t]*fc_w pairs                   112
//  H0   [32k][320t] (hA,hB) packed                  10240
//  H1   [32k][320t] (hA,hB) packed                  10240
// total = 23856 u64 = 190848 B
#define SMEM_U64S 23856
#define SMEM_BYTES (SMEM_U64S * 8)

extern "C" __global__ void __launch_bounds__(NT, 1)
lstm_b262144_kernel(
    const float* __restrict__ x,
    const float* __restrict__ Wih0, const float* __restrict__ Whh0,
    const float* __restrict__ bih0, const float* __restrict__ bhh0,
    const float* __restrict__ Wih1, const float* __restrict__ Whh1,
    const float* __restrict__ bih1, const float* __restrict__ bhh1,
    const float* __restrict__ fcw,  const float* __restrict__ fcb,
    const float* __restrict__ fc1w, const float* __restrict__ fc1b,
    float* __restrict__ out, int B)
{
    extern __shared__ u64 sm[];
    u64* WLs = sm;
    u64* B0  = WLs + 3072;
    u64* WI0 = B0 + 64;
    u64* B1  = WI0 + 64;
    u64* WO  = B1 + 64;
    u64* H0  = WO + 112;
    u64* H1  = H0 + 32 * NT;

    const int tid = threadIdx.x;

    // ---- SMEM half-weights: s=4..7 (gates g,o). idx = m*1024+c*128+k*4+(s-4)
    for (int d = tid; d < 3072; d += NT) {
        int m = d >> 10, r = d & 1023;
        int c = r >> 7, k = (r >> 2) & 31, s = (r & 3) + 4;
        int g = s >> 1, sub = s & 1;
        int r0 = g * 32 + 4 * c + 2 * sub;
        const float* W = (m == 0) ? Whh0 : (m == 1) ? Wih1 : Whh1;
        WLs[d] = pk2(W[r0 * 32 + k], W[(r0 + 1) * 32 + k]);
    }
    if (tid < 128) {
        ((float*)B0)[tid]  = bih0[tid] + bhh0[tid];
        ((float*)WI0)[tid] = Wih0[tid];
        ((float*)B1)[tid]  = bih1[tid] + bhh1[tid];
    }
    {
        float* WOf = (float*)WO;
        for (int d = tid; d < 224; d += NT) WOf[d] = fc1w[d >> 5] * fcw[d & 31];
    }
#pragma unroll
    for (int u = 0; u < 32; u++) {
        H0[u * NT + tid] = 0ull;
        H1[u * NT + tid] = 0ull;
    }
    __syncthreads();

    const long long Bll = B;
    const long long eA = (long long)blockIdx.x * EPC + tid;
    if (eA >= Bll) return;
    const long long eB = eA + NT;
    const bool storeB = (eB < Bll);
    const long long eBs = storeB ? eB : eA;  // clamp (duplicate compute)

    float xa[7], xb[7];
#pragma unroll
    for (int t = 0; t < 7; t++) { xa[t] = x[eA * 7 + t]; xb[t] = x[eBs * 7 + t]; }

    u64 hn[32];
    u64 acca = 0ull, accb = 0ull;
    u64 dmy = 0ull;

#pragma unroll 1
    for (int t = 0; t < 7; t++) {
        u64 x2a = bc2(xa[t]), x2b = bc2(xb[t]);

        // ========================= layer 0 =========================
#pragma unroll
        for (int c = 0; c < 8; c++) {
            const int p0 = 2 * c;
            u64 ca0 = 0ull, cb0 = 0ull, ca1 = 0ull, cb1 = 0ull;
            u64* r0 = g_cstate + (u64)p0 * BMAX;
            u64* r1 = g_cstate + (u64)(p0 + 1) * BMAX;
            if (t) {
                ca0 = r0[eA]; cb0 = r0[eBs];
                ca1 = r1[eA]; cb1 = r1[eBs];
            }

            u64 wi0 = WI0[p0], wi1 = WI0[p0 + 1];
            u64 wf0 = WI0[p0 + 16], wf1 = WI0[p0 + 17];
            u64 wg0 = WI0[p0 + 32], wg1 = WI0[p0 + 33];
            u64 wo0 = WI0[p0 + 48], wo1 = WI0[p0 + 49];
            u64 zai0 = fma2(x2a, wi0, B0[p0]),      zbi0 = fma2(x2b, wi0, B0[p0]);
            u64 zai1 = fma2(x2a, wi1, B0[p0 + 1]),  zbi1 = fma2(x2b, wi1, B0[p0 + 1]);
            u64 zaf0 = fma2(x2a, wf0, B0[p0 + 16]), zbf0 = fma2(x2b, wf0, B0[p0 + 16]);
            u64 zaf1 = fma2(x2a, wf1, B0[p0 + 17]), zbf1 = fma2(x2b, wf1, B0[p0 + 17]);
            u64 zag0 = fma2(x2a, wg0, B0[p0 + 32]), zbg0 = fma2(x2b, wg0, B0[p0 + 32]);
            u64 zag1 = fma2(x2a, wg1, B0[p0 + 33]), zbg1 = fma2(x2b, wg1, B0[p0 + 33]);
            u64 zao0 = fma2(x2a, wo0, B0[p0 + 48]), zbo0 = fma2(x2b, wo0, B0[p0 + 48]);
            u64 zao1 = fma2(x2a, wo1, B0[p0 + 49]), zbo1 = fma2(x2b, wo1, B0[p0 + 49]);

            const int cb = c * 64;  // const base (m=0)
            const ulonglong2* wps = (const ulonglong2*)(WLs) + c * 64;
#pragma unroll 8
            for (int k = 0; k < 32; k++) {
                ulonglong2 q0 = cW[cb + 2 * k + 0];
                ulonglong2 q1 = cW[cb + 2 * k + 1];
                ulonglong2 q2 = wps[2 * k + 0];
                ulonglong2 q3 = wps[2 * k + 1];
                float ha, hb; upk2(H0[k * NT + tid], ha, hb);
                u64 hka = bc2(ha), hkb = bc2(hb);
                zai0 = fma2(hka, q0.x, zai0); zbi0 = fma2(hkb, q0.x, zbi0);
                zai1 = fma2(hka, q0.y, zai1); zbi1 = fma2(hkb, q0.y, zbi1);
                zaf0 = fma2(hka, q1.x, zaf0); zbf0 = fma2(hkb, q1.x, zbf0);
                zaf1 = fma2(hka, q1.y, zaf1); zbf1 = fma2(hkb, q1.y, zbf1);
                zag0 = fma2(hka, q2.x, zag0); zbg0 = fma2(hkb, q2.x, zbg0);
                zag1 = fma2(hka, q2.y, zag1); zbg1 = fma2(hkb, q2.y, zbg1);
                zao0 = fma2(hka, q3.x, zao0); zbo0 = fma2(hkb, q3.x, zbo0);
                zao1 = fma2(hka, q3.y, zao1); zbo1 = fma2(hkb, q3.y, zbo1);
            }
            u64 h2a0 = lstm_upd<false>(zai0, zaf0, zag0, zao0, ca0, 0ull, dmy);
            u64 h2b0 = lstm_upd<false>(zbi0, zbf0, zbg0, zbo0, cb0, 0ull, dmy);
            u64 h2a1 = lstm_upd<false>(zai1, zaf1, zag1, zao1, ca1, 0ull, dmy);
            u64 h2b1 = lstm_upd<false>(zbi1, zbf1, zbg1, zbo1, cb1, 0ull, dmy);
            if (t < 6) {
                r0[eA] = ca0; r0[eBs] = cb0;
                r1[eA] = ca1; r1[eBs] = cb1;
            }
            float a0, a1, b0v, b1v;
            upk2(h2a0, a0, a1); upk2(h2b0, b0v, b1v);
            hn[4 * c + 0] = pk2(a0, b0v); hn[4 * c + 1] = pk2(a1, b1v);
            upk2(h2a1, a0, a1); upk2(h2b1, b0v, b1v);
            hn[4 * c + 2] = pk2(a0, b0v); hn[4 * c + 3] = pk2(a1, b1v);
        }
#pragma unroll
        for (int u = 0; u < 32; u++) H0[u * NT + tid] = hn[u];

        // ========================= layer 1 =========================
#pragma unroll
        for (int c = 0; c < 8; c++) {
            const int p0 = 2 * c;
            u64 ca0 = 0ull, cb0 = 0ull, ca1 = 0ull, cb1 = 0ull;
            u64* r0 = g_cstate + (u64)(16 + p0) * BMAX;
            u64* r1 = g_cstate + (u64)(16 + p0 + 1) * BMAX;
            if (t) {
                ca0 = r0[eA]; cb0 = r0[eBs];
                ca1 = r1[eA]; cb1 = r1[eBs];
            }

            u64 zai0 = B1[p0],      zai1 = B1[p0 + 1];
            u64 zaf0 = B1[p0 + 16], zaf1 = B1[p0 + 17];
            u64 zag0 = B1[p0 + 32], zag1 = B1[p0 + 33];
            u64 zao0 = B1[p0 + 48], zao1 = B1[p0 + 49];
            u64 zbi0 = zai0, zbi1 = zai1;
            u64 zbf0 = zaf0, zbf1 = zaf1;
            u64 zbg0 = zag0, zbg1 = zag1;
            u64 zbo0 = zao0, zbo1 = zao1;

            {   // x-projection: Wih1 (m=1)
                const int cb = 512 + c * 64;
                const ulonglong2* wps = (const ulonglong2*)(WLs + 1024) + c * 64;
#pragma unroll 8
                for (int k = 0; k < 32; k++) {
                    ulonglong2 q0 = cW[cb + 2 * k + 0];
                    ulonglong2 q1 = cW[cb + 2 * k + 1];
                    ulonglong2 q2 = wps[2 * k + 0];
                    ulonglong2 q3 = wps[2 * k + 1];
                    float ha, hb; upk2(H0[k * NT + tid], ha, hb);
                    u64 hka = bc2(ha), hkb = bc2(hb);
                    zai0 = fma2(hka, q0.x, zai0); zbi0 = fma2(hkb, q0.x, zbi0);
                    zai1 = fma2(hka, q0.y, zai1); zbi1 = fma2(hkb, q0.y, zbi1);
                    zaf0 = fma2(hka, q1.x, zaf0); zbf0 = fma2(hkb, q1.x, zbf0);
                    zaf1 = fma2(hka, q1.y, zaf1); zbf1 = fma2(hkb, q1.y, zbf1);
                    zag0 = fma2(hka, q2.x, zag0); zbg0 = fma2(hkb, q2.x, zbg0);
                    zag1 = fma2(hka, q2.y, zag1); zbg1 = fma2(hkb, q2.y, zbg1);
                    zao0 = fma2(hka, q3.x, zao0); zbo0 = fma2(hkb, q3.x, zbo0);
                    zao1 = fma2(hka, q3.y, zao1); zbo1 = fma2(hkb, q3.y, zbo1);
                }
            }
            {   // h-projection: Whh1 (m=2)
                const int cb = 1024 + c * 64;
                const ulonglong2* wps = (const ulonglong2*)(WLs + 2048) + c * 64;
#pragma unroll 8
                for (int k = 0; k < 32; k++) {
                    ulonglong2 q0 = cW[cb + 2 * k + 0];
                    ulonglong2 q1 = cW[cb + 2 * k + 1];
                    ulonglong2 q2 = wps[2 * k + 0];
                    ulonglong2 q3 = wps[2 * k + 1];
                    float ha, hb; upk2(H1[k * NT + tid], ha, hb);
                    u64 hka = bc2(ha), hkb = bc2(hb);
                    zai0 = fma2(hka, q0.x, zai0); zbi0 = fma2(hkb, q0.x, zbi0);
                    zai1 = fma2(hka, q0.y, zai1); zbi1 = fma2(hkb, q0.y, zbi1);
                    zaf0 = fma2(hka, q1.x, zaf0); zbf0 = fma2(hkb, q1.x, zbf0);
                    zaf1 = fma2(hka, q1.y, zaf1); zbf1 = fma2(hkb, q1.y, zbf1);
                    zag0 = fma2(hka, q2.x, zag0); zbg0 = fma2(hkb, q2.x, zbg0);
                    zag1 = fma2(hka, q2.y, zag1); zbg1 = fma2(hkb, q2.y, zbg1);
                    zao0 = fma2(hka, q3.x, zao0); zbo0 = fma2(hkb, q3.x, zbo0);
                    zao1 = fma2(hka, q3.y, zao1); zbo1 = fma2(hkb, q3.y, zbo1);
                }
            }
            u64 wo_p0 = WO[t * 16 + p0], wo_p1 = WO[t * 16 + p0 + 1];
            u64 h2a0 = lstm_upd<true>(zai0, zaf0, zag0, zao0, ca0, wo_p0, acca);
            u64 h2b0 = lstm_upd<true>(zbi0, zbf0, zbg0, zbo0, cb0, wo_p0, accb);
            u64 h2a1 = lstm_upd<true>(zai1, zaf1, zag1, zao1, ca1, wo_p1, acca);
            u64 h2b1 = lstm_upd<true>(zbi1, zbf1, zbg1, zbo1, cb1, wo_p1, accb);
            if (t < 6) {
                r0[eA] = ca0; r0[eBs] = cb0;
                r1[eA] = ca1; r1[eBs] = cb1;
            }
            float a0, a1, b0v, b1v;
            upk2(h2a0, a0, a1); upk2(h2b0, b0v, b1v);
            hn[4 * c + 0] = pk2(a0, b0v); hn[4 * c + 1] = pk2(a1, b1v);
            upk2(h2a1, a0, a1); upk2(h2b1, b0v, b1v);
            hn[4 * c + 2] = pk2(a0, b0v); hn[4 * c + 3] = pk2(a1, b1v);
        }
#pragma unroll
        for (int u = 0; u < 32; u++) H1[u * NT + tid] = hn[u];
    }

    float s = 0.0f;
#pragma unroll
    for (int t = 0; t < 7; t++) s += fc1w[t];
    float bias = fcb[0] * s + fc1b[0];

    float alo, ahi; upk2(acca, alo, ahi);
    out[eA] = alo + ahi + bias;
    if (storeB) {
        float blo, bhi; upk2(accb, blo, bhi);
        out[eB] = blo + bhi + bias;
    }
}

extern "C" void kernel_launch(void* const* d_in, const int* in_sizes, int n_in,
                              void* d_out, int out_size) {
    const float* x    = (const float*)d_in[0];
    const float* Wih0 = (const float*)d_in[1];
    const float* Whh0 = (const float*)d_in[2];
    const float* bih0 = (const float*)d_in[3];
    const float* bhh0 = (const float*)d_in[4];
    const float* Wih1 = (const float*)d_in[5];
    const float* Whh1 = (const float*)d_in[6];
    const float* bih1 = (const float*)d_in[7];
    const float* bhh1 = (const float*)d_in[8];
    const float* fcw  = (const float*)d_in[9];
    const float* fcb  = (const float*)d_in[10];
    const float* fc1w = (const float*)d_in[11];
    const float* fc1b = (const float*)d_in[12];
    float* out = (float*)d_out;

    const int B = in_sizes[0] / 7;  // [B, T=7, F=1]

    cudaFuncSetAttribute(lstm_b262144_kernel,
                         cudaFuncAttributeMaxDynamicSharedMemorySize, SMEM_BYTES);

    // 1) repack gate-i/f weight pairs into staging buffer
    lstm_wpack_kernel<<<3, 1024>>>(Whh0, Wih1, Whh1);

    // 2) D2D copy staging -> __constant__ cW (graph-capturable memcpy node)
    void* cdst = nullptr; void* csrc = nullptr;
    cudaGetSymbolAddress(&cdst, cW);        // host-side query, capture-safe
    cudaGetSymbolAddress(&csrc, g_wpack);
    cudaMemcpyAsync(cdst, csrc, 1536 * sizeof(ulonglong2),
                    cudaMemcpyDeviceToDevice);

    // 3) main kernel
    int grid = (B + EPC - 1) / EPC;
    lstm_b262144_kernel<<<grid, NT, SMEM_BYTES>>>(
        x, Wih0, Whh0, bih0, bhh0, Wih1, Whh1, bih1, bhh1,
        fcw, fcb, fc1w, fc1b, out, B);
}